// round 14
// baseline (speedup 1.0000x reference)
#include <cuda_runtime.h>
#include <math.h>
#include <stdint.h>

#define SEQ 4096
#define DM  1024
#define DK  128

// ---- proj tiling (R12 known-good) ----
#define PM   64
#define PKC  32
#define PNCH (DM / PKC)   // 32 chunks
#define XP   36           // Xs stride
#define WP   136          // Ws stride (mod 32 = 8)

// ---- attention tiling: BMA=128, 256 thr, 144 blocks, single wave ----
#define BMA   128
#define BNA   32
#define CHUNK 512
#define NTA   (SEQ / BMA)  // 32
#define MAXCH 8            // max chunks per tile = ceil(32*128/512) = 8
#define ABLOCKS 144        // sum_{tier=1..8} 4*tier
#define KP  136            // K/V smem stride (mod 32 = 8: LDS.64 conflict-free)
#define PP  36
#define KST (32 * KP)      // 4352 floats per buffer

// ---- scratch ----
__device__ float g_qp[SEQ * DK];   // d-permuted within 8-col groups
__device__ float g_kp[SEQ * DK];   // d-permuted within 8-col groups
__device__ float g_vp[SEQ * DK];   // plain layout
__device__ float g_pO[NTA * MAXCH * BMA * DK];
__device__ float g_pm[NTA * MAXCH * BMA];
__device__ float g_pl[NTA * MAXCH * BMA];

__device__ __forceinline__ float f2tf(float f) {
    uint32_t u;
    asm("cvt.rn.tf32.f32 %0, %1;" : "=r"(u) : "f"(f));
    return __uint_as_float(u);
}

__device__ __forceinline__ void mma8(float& d0, float& d1, float& d2, float& d3,
                                     uint32_t a0, uint32_t a1, uint32_t a2, uint32_t a3,
                                     uint32_t b0, uint32_t b1)
{
    asm volatile(
        "mma.sync.aligned.m16n8k8.row.col.f32.tf32.tf32.f32 "
        "{%0,%1,%2,%3}, {%4,%5,%6,%7}, {%8,%9}, {%0,%1,%2,%3};\n"
        : "+f"(d0), "+f"(d1), "+f"(d2), "+f"(d3)
        : "r"(a0), "r"(a1), "r"(a2), "r"(a3), "r"(b0), "r"(b1));
}

__device__ __forceinline__ uint32_t ldu(const float* p)    { return __float_as_uint(*p); }
__device__ __forceinline__ uint32_t ldu_rn(const float* p) { return __float_as_uint(*p) + 0x1000u; }
__device__ __forceinline__ uint32_t fb(float f)            { return __float_as_uint(f); }

__device__ __forceinline__ void cp16(void* dst_smem, const void* src_gmem) {
    uint32_t d = (uint32_t)__cvta_generic_to_shared(dst_smem);
    asm volatile("cp.async.cg.shared.global [%0], [%1], 16;" :: "r"(d), "l"(src_gmem));
}
#define CP_COMMIT() asm volatile("cp.async.commit_group;")
#define CP_WAIT(n)  asm volatile("cp.async.wait_group %0;" :: "n"(n))

// ---------------------------------------------------------------------------
// Projection (exact R12): OUT = round_tf32((X @ W + b) * osc). 256 thr,
// tile 64 x 128, 3-stage cp.async, one sync per chunk. W rounded at frag load.
// q/k outputs stored with d-permutation p(j)=2(j&3)+(j>>2) within 8-groups.
// ---------------------------------------------------------------------------
__global__ void __launch_bounds__(256, 2) proj_kernel(
    const float* __restrict__ q, const float* __restrict__ k, const float* __restrict__ v,
    const float* __restrict__ Wq, const float* __restrict__ bq,
    const float* __restrict__ Wk, const float* __restrict__ bk,
    const float* __restrict__ Wv, const float* __restrict__ bv)
{
    extern __shared__ float psm[];
    float* Xb = psm;                   // 3 x 64 x 36
    float* Wb = psm + 3 * PM * XP;     // 3 x 32 x 136

    const int which = blockIdx.y;
    const float* X = (which == 0) ? q  : (which == 1) ? k  : v;
    const float* W = (which == 0) ? Wq : (which == 1) ? Wk : Wv;
    const float* B = (which == 0) ? bq : (which == 1) ? bk : bv;
    float* OUT     = (which == 0) ? g_qp : (which == 1) ? g_kp : g_vp;
    const float osc = (which == 0) ? 0.08838834764831845f : 1.0f;

    const int t    = threadIdx.x;
    const int warp = t >> 5;
    const int lane = t & 31;
    const int wr   = warp >> 2;
    const int wc   = warp & 3;
    const int g    = lane >> 2;
    const int tig  = lane & 3;
    const int r0   = blockIdx.x * PM;

    auto issue = [&](int kc) {
        const int k0 = kc * PKC;
        float* Xs = Xb + (kc % 3) * PM * XP;
        float* Ws = Wb + (kc % 3) * PKC * WP;
#pragma unroll
        for (int i = 0; i < 2; i++) {
            int idx = t + i * 256;
            int row = idx >> 3, c4 = idx & 7;
            cp16(&Xs[row * XP + c4 * 4], &X[(r0 + row) * DM + k0 + c4 * 4]);
        }
#pragma unroll
        for (int i = 0; i < 4; i++) {
            int idx = t + i * 256;
            int row = idx >> 5, c4 = idx & 31;
            cp16(&Ws[row * WP + c4 * 4], &W[(k0 + row) * DK + c4 * 4]);
        }
        CP_COMMIT();
    };

    float acc[8][4];
#pragma unroll
    for (int i = 0; i < 8; i++)
#pragma unroll
        for (int j = 0; j < 4; j++) acc[i][j] = 0.f;

    issue(0);
    issue(1);

    for (int kc = 0; kc < PNCH; kc++) {
        if (kc + 1 < PNCH) { CP_WAIT(1); } else { CP_WAIT(0); }
        __syncthreads();
        if (kc + 2 < PNCH) issue(kc + 2);

        const float* Xs = Xb + (kc % 3) * PM * XP;
        const float* Ws = Wb + (kc % 3) * PKC * WP;

#pragma unroll
        for (int ks = 0; ks < 4; ks++) {
            const int kk = ks * 8;
            uint32_t a[2][4];
#pragma unroll
            for (int mf = 0; mf < 2; mf++) {
                const float* ab = &Xs[(wr * 32 + mf * 16 + g) * XP + kk + tig];
                a[mf][0] = ldu_rn(ab);
                a[mf][1] = ldu_rn(ab + 8 * XP);
                a[mf][2] = ldu_rn(ab + 4);
                a[mf][3] = ldu_rn(ab + 8 * XP + 4);
            }
            uint32_t b[4][2];
#pragma unroll
            for (int nf = 0; nf < 4; nf++) {
                b[nf][0] = ldu_rn(&Ws[(kk + tig) * WP + wc * 32 + nf * 8 + g]);
                b[nf][1] = ldu_rn(&Ws[(kk + tig + 4) * WP + wc * 32 + nf * 8 + g]);
            }
#pragma unroll
            for (int mf = 0; mf < 2; mf++)
#pragma unroll
                for (int nf = 0; nf < 4; nf++)
                    mma8(acc[mf * 4 + nf][0], acc[mf * 4 + nf][1],
                         acc[mf * 4 + nf][2], acc[mf * 4 + nf][3],
                         a[mf][0], a[mf][1], a[mf][2], a[mf][3],
                         b[nf][0], b[nf][1]);
        }
    }

    // epilogue
    const int j0 = 2 * tig, j1 = j0 + 1;
    const int p0 = 2 * (j0 & 3) + (j0 >> 2);
    const int p1 = 2 * (j1 & 3) + (j1 >> 2);
#pragma unroll
    for (int mf = 0; mf < 2; mf++) {
        const int row0 = r0 + wr * 32 + mf * 16 + g;
        const int row1 = row0 + 8;
#pragma unroll
        for (int nf = 0; nf < 4; nf++) {
            int colb = wc * 32 + nf * 8;
            float2 bb = *reinterpret_cast<const float2*>(&B[colb + j0]);
            float v00 = f2tf((acc[mf * 4 + nf][0] + bb.x) * osc);
            float v01 = f2tf((acc[mf * 4 + nf][1] + bb.y) * osc);
            float v10 = f2tf((acc[mf * 4 + nf][2] + bb.x) * osc);
            float v11 = f2tf((acc[mf * 4 + nf][3] + bb.y) * osc);
            if (which == 2) {   // V plain layout, float2
                float2 o0; o0.x = v00; o0.y = v01;
                float2 o1; o1.x = v10; o1.y = v11;
                *reinterpret_cast<float2*>(&OUT[row0 * DK + colb + j0]) = o0;
                *reinterpret_cast<float2*>(&OUT[row1 * DK + colb + j0]) = o1;
            } else {            // Q/K permuted, scalar
                OUT[row0 * DK + colb + p0] = v00;
                OUT[row0 * DK + colb + p1] = v01;
                OUT[row1 * DK + colb + p0] = v10;
                OUT[row1 * DK + colb + p1] = v11;
            }
        }
    }
}

// ---------------------------------------------------------------------------
// Split-KV causal flash attention partials. BMA=128, 256 thr (8 warps x 16
// rows), 1 block/SM, 3-stage cp.async, separate P buffer, Q frags in regs.
// Per-warp layout identical to the proven 64-row version; K/V traffic halved.
// ---------------------------------------------------------------------------
__global__ void __launch_bounds__(256) attn_part_kernel()
{
    extern __shared__ float sm[];
    float* Kb = sm;                 // 3 x 32 x 136
    float* Vb = sm + 3 * KST;       // 3 x 32 x 136
    float* Ps = sm + 6 * KST;       // 8 x 16 x 36

    const int t    = threadIdx.x;
    const int warp = t >> 5;        // 0..7
    const int lane = t & 31;
    const int g    = lane >> 2;
    const int tig  = lane & 3;
    float* Pw = Ps + warp * (16 * PP);

    // heavy-first decode: tile r (0..31) has (r/4)+1 chunks; tier has 4 tiles
    int Bd = ABLOCKS - 1 - (int)blockIdx.x;
    int tier = 1, rem = Bd;
    while (rem >= 4 * tier) { rem -= 4 * tier; tier++; }
    const int r = 4 * (tier - 1) + rem / tier;
    const int c = rem % tier;

    const int rbase  = r * BMA;
    const int c0base = c * CHUNK;
    const int colend = min(c0base + CHUNK, rbase + BMA);
    const int nct    = (colend - c0base) / BNA;   // 4..16

    auto issue_kv = [&](int tc) {
        const int c0 = c0base + tc * BNA;
        float* Kd = Kb + (tc % 3) * KST;
        float* Vd = Vb + ((tc + 2) % 3) * KST;
#pragma unroll
        for (int i = 0; i < 4; i++) {
            int idx = t + i * 256;
            int row = idx >> 5, c4 = idx & 31;
            cp16(&Kd[row * KP + c4 * 4], &g_kp[(c0 + row) * DK + c4 * 4]);
            cp16(&Vd[row * KP + c4 * 4], &g_vp[(c0 + row) * DK + c4 * 4]);
        }
        CP_COMMIT();
    };

    // group 1: Q (128 rows) -> buffers K0,K1,K2,V0 (contiguous 4 x 32 rows)
#pragma unroll
    for (int i = 0; i < 16; i++) {
        int idx = t + i * 256;
        int row = idx >> 5, c4 = idx & 31;   // row 0..127
        cp16(&sm[(row >> 5) * KST + (row & 31) * KP + c4 * 4],
             &g_qp[(rbase + row) * DK + c4 * 4]);
    }
    CP_COMMIT();
    CP_WAIT(0);
    __syncthreads();

    // cache Q A-fragments (permuted layout -> float2); warp w uses buffer w>>1
    uint32_t qf[16][4];
    {
        const float* Qsrc = sm + (warp >> 1) * KST;
        const int row_l = (warp & 1) * 16 + g;
#pragma unroll
        for (int ks = 0; ks < 16; ks++) {
            float2 qa = *reinterpret_cast<const float2*>(&Qsrc[row_l * KP + ks * 8 + 2 * tig]);
            float2 qb = *reinterpret_cast<const float2*>(&Qsrc[(row_l + 8) * KP + ks * 8 + 2 * tig]);
            qf[ks][0] = fb(qa.x);
            qf[ks][1] = fb(qb.x);
            qf[ks][2] = fb(qa.y);
            qf[ks][3] = fb(qb.y);
        }
    }
    __syncthreads();      // all Q fragments read; buffers free
    issue_kv(0);
    issue_kv(1);

    float o[16][4];
#pragma unroll
    for (int nt = 0; nt < 16; nt++)
#pragma unroll
        for (int j = 0; j < 4; j++) o[nt][j] = 0.f;

    float m0 = -1e30f, m1 = -1e30f, l0 = 0.f, l1 = 0.f;
    const int grow0 = rbase + warp * 16 + g;
    const int grow1 = grow0 + 8;

    for (int tc = 0; tc < nct; tc++) {
        const int c0 = c0base + tc * BNA;
        if (tc + 1 < nct) { CP_WAIT(1); } else { CP_WAIT(0); }
        __syncthreads();
        if (tc + 2 < nct) issue_kv(tc + 2);

        const float* Ks = Kb + (tc % 3) * KST;
        const float* Vs = Vb + ((tc + 2) % 3) * KST;

        // ---- S = Q K^T ----
        float s[4][4];
#pragma unroll
        for (int nt = 0; nt < 4; nt++)
#pragma unroll
            for (int j = 0; j < 4; j++) s[nt][j] = 0.f;

#pragma unroll
        for (int ks = 0; ks < 16; ks++) {
            const int kk = ks * 8;
#pragma unroll
            for (int nt = 0; nt < 4; nt++) {
                float2 kv = *reinterpret_cast<const float2*>(&Ks[(nt * 8 + g) * KP + kk + 2 * tig]);
                mma8(s[nt][0], s[nt][1], s[nt][2], s[nt][3],
                     qf[ks][0], qf[ks][1], qf[ks][2], qf[ks][3],
                     fb(kv.x), fb(kv.y));
            }
        }

        // ---- causal mask + online softmax ----
        float mloc0 = -1e30f, mloc1 = -1e30f;
#pragma unroll
        for (int nt = 0; nt < 4; nt++) {
            int colb = c0 + nt * 8 + 2 * tig;
            float x0 = (colb     <= grow0) ? s[nt][0] : -1e30f;
            float x1 = (colb + 1 <= grow0) ? s[nt][1] : -1e30f;
            float x2 = (colb     <= grow1) ? s[nt][2] : -1e30f;
            float x3 = (colb + 1 <= grow1) ? s[nt][3] : -1e30f;
            s[nt][0] = x0; s[nt][1] = x1; s[nt][2] = x2; s[nt][3] = x3;
            mloc0 = fmaxf(mloc0, fmaxf(x0, x1));
            mloc1 = fmaxf(mloc1, fmaxf(x2, x3));
        }
        mloc0 = fmaxf(mloc0, __shfl_xor_sync(0xffffffffu, mloc0, 1));
        mloc0 = fmaxf(mloc0, __shfl_xor_sync(0xffffffffu, mloc0, 2));
        mloc1 = fmaxf(mloc1, __shfl_xor_sync(0xffffffffu, mloc1, 1));
        mloc1 = fmaxf(mloc1, __shfl_xor_sync(0xffffffffu, mloc1, 2));

        float mn0 = fmaxf(m0, mloc0);
        float mn1 = fmaxf(m1, mloc1);
        float sc0 = __expf(m0 - mn0);
        float sc1 = __expf(m1 - mn1);

        float ps0 = 0.f, ps1 = 0.f;
#pragma unroll
        for (int nt = 0; nt < 4; nt++) {
            float p0 = __expf(s[nt][0] - mn0);
            float p1 = __expf(s[nt][1] - mn0);
            float p2 = __expf(s[nt][2] - mn1);
            float p3 = __expf(s[nt][3] - mn1);
            ps0 += p0 + p1;
            ps1 += p2 + p3;
            float* d0 = &Pw[g * PP + nt * 8 + 2 * tig];
            d0[0] = f2tf(p0); d0[1] = f2tf(p1);
            float* d1 = &Pw[(g + 8) * PP + nt * 8 + 2 * tig];
            d1[0] = f2tf(p2); d1[1] = f2tf(p3);
        }
        ps0 += __shfl_xor_sync(0xffffffffu, ps0, 1);
        ps0 += __shfl_xor_sync(0xffffffffu, ps0, 2);
        ps1 += __shfl_xor_sync(0xffffffffu, ps1, 1);
        ps1 += __shfl_xor_sync(0xffffffffu, ps1, 2);

        l0 = l0 * sc0 + ps0;  m0 = mn0;
        l1 = l1 * sc1 + ps1;  m1 = mn1;

        __syncwarp();

        // ---- rescale O, then O += P @ V ----
#pragma unroll
        for (int nt = 0; nt < 16; nt++) {
            o[nt][0] *= sc0; o[nt][1] *= sc0;
            o[nt][2] *= sc1; o[nt][3] *= sc1;
        }

#pragma unroll
        for (int ks = 0; ks < 4; ks++) {
            const int kk = ks * 8;
            const float* ab = &Pw[g * PP + kk + tig];
            uint32_t a0 = ldu(ab);
            uint32_t a1 = ldu(ab + 8 * PP);
            uint32_t a2 = ldu(ab + 4);
            uint32_t a3 = ldu(ab + 8 * PP + 4);
#pragma unroll
            for (int nt = 0; nt < 16; nt++) {
                uint32_t b0 = ldu(&Vs[(kk + tig) * KP + nt * 8 + g]);
                uint32_t b1 = ldu(&Vs[(kk + tig + 4) * KP + nt * 8 + g]);
                mma8(o[nt][0], o[nt][1], o[nt][2], o[nt][3], a0, a1, a2, a3, b0, b1);
            }
        }
    }

    // ---- write unnormalized partials ----
    const int pidx = r * MAXCH + c;
    float* baseO = &g_pO[(size_t)pidx * BMA * DK];
    const int row0 = warp * 16 + g;
    const int row1 = row0 + 8;
#pragma unroll
    for (int nt = 0; nt < 16; nt++) {
        int col = nt * 8 + 2 * tig;
        float2 w0; w0.x = o[nt][0]; w0.y = o[nt][1];
        float2 w1; w1.x = o[nt][2]; w1.y = o[nt][3];
        *reinterpret_cast<float2*>(&baseO[row0 * DK + col]) = w0;
        *reinterpret_cast<float2*>(&baseO[row1 * DK + col]) = w1;
    }
    if (tig == 0) {
        g_pm[pidx * BMA + row0] = m0;
        g_pm[pidx * BMA + row1] = m1;
        g_pl[pidx * BMA + row0] = l0;
        g_pl[pidx * BMA + row1] = l1;
    }
}

// ---------------------------------------------------------------------------
// Merge: 1024 blocks, block (r, part) does 4 rows x 128 d (1 float4/thread).
// nch = (r>>2)+1 for BMA=128 tiles.
// ---------------------------------------------------------------------------
__global__ void __launch_bounds__(128) merge_kernel(float* __restrict__ out)
{
    __shared__ float s_m[4 * MAXCH];
    __shared__ float s_l[4 * MAXCH];
    __shared__ float s_w[4 * MAXCH];
    __shared__ float s_inv[4];

    const int r    = blockIdx.x >> 5;   // 0..31
    const int part = blockIdx.x & 31;   // 0..31 (4 rows each)
    const int nch  = (r >> 2) + 1;
    const int t    = threadIdx.x;

    if (t < 32) {
        int row4 = t >> 3, ch = t & 7;
        if (ch < nch) {
            s_m[t] = g_pm[(r * MAXCH + ch) * BMA + part * 4 + row4];
            s_l[t] = g_pl[(r * MAXCH + ch) * BMA + part * 4 + row4];
        } else {
            s_m[t] = -1e30f; s_l[t] = 0.f;
        }
    }
    __syncthreads();

    if (t < 4) {
        float mx = -1e30f;
#pragma unroll
        for (int ch = 0; ch < MAXCH; ch++) mx = fmaxf(mx, s_m[t * 8 + ch]);
        float den = 0.f;
#pragma unroll
        for (int ch = 0; ch < MAXCH; ch++) {
            float w = __expf(s_m[t * 8 + ch] - mx);
            s_w[t * 8 + ch] = w;
            den += w * s_l[t * 8 + ch];
        }
        s_inv[t] = 1.f / den;
    }
    __syncthreads();

    {
        int row4 = t >> 5, d4 = t & 31;          // 128 = 4 rows x 32 float4
        int growl = part * 4 + row4;
        float4 acc; acc.x = acc.y = acc.z = acc.w = 0.f;
#pragma unroll
        for (int ch = 0; ch < MAXCH; ch++) {
            if (ch < nch) {
                float4 p = reinterpret_cast<const float4*>(
                    &g_pO[((size_t)(r * MAXCH + ch) * BMA + growl) * DK])[d4];
                float w = s_w[row4 * 8 + ch];
                acc.x += w * p.x; acc.y += w * p.y;
                acc.z += w * p.z; acc.w += w * p.w;
            }
        }
        float inv = s_inv[row4];
        acc.x *= inv; acc.y *= inv; acc.z *= inv; acc.w *= inv;
        reinterpret_cast<float4*>(&out[(r * BMA + growl) * DK])[d4] = acc;
    }
}

// ---------------------------------------------------------------------------
extern "C" void kernel_launch(void* const* d_in, const int* in_sizes, int n_in,
                              void* d_out, int out_size)
{
    const float* q  = (const float*)d_in[0];
    const float* k  = (const float*)d_in[1];
    const float* v  = (const float*)d_in[2];
    const float* Wq = (const float*)d_in[3];
    const float* bq = (const float*)d_in[4];
    const float* Wk = (const float*)d_in[5];
    const float* bk = (const float*)d_in[6];
    const float* Wv = (const float*)d_in[7];
    const float* bv = (const float*)d_in[8];
    float* out = (float*)d_out;

    const int smem_proj = 3 * (PM * XP + PKC * WP) * sizeof(float);        // 79872
    const int smem_attn = (6 * KST + 8 * 16 * PP) * sizeof(float);         // 122880
    cudaFuncSetAttribute(proj_kernel, cudaFuncAttributeMaxDynamicSharedMemorySize, smem_proj);
    cudaFuncSetAttribute(attn_part_kernel, cudaFuncAttributeMaxDynamicSharedMemorySize, smem_attn);

    proj_kernel<<<dim3(SEQ / PM, 3), 256, smem_proj>>>(q, k, v, Wq, bq, Wk, bk, Wv, bv);
    attn_part_kernel<<<ABLOCKS, 256, smem_attn>>>();
    merge_kernel<<<NTA * 32, 128>>>(out);
}

// round 15
// speedup vs baseline: 1.1409x; 1.1409x over previous
#include <cuda_runtime.h>
#include <math.h>
#include <stdint.h>

#define SEQ 4096
#define DM  1024
#define DK  128

// ---- proj tiling: split-K (2 halves), 64x128 tiles, 2-stage pipeline ----
#define PM   64
#define PKC  32
#define KHALF 16          // chunks per k-half (16 * 32 = 512)
#define XP   36           // Xs stride
#define WP   136          // Ws stride (mod 32 = 8)

// ---- attention tiling (R12 known-good) ----
#define BMA   64
#define BNA   32
#define CHUNK 512
#define NTA   (SEQ / BMA)
#define MAXCH 8
#define ABLOCKS 288       // sum_{tier=1..8} 8*tier
#define KP  136           // K/V smem stride (mod 32 = 8: LDS.64 conflict-free)
#define PP  36
#define KST (32 * KP)     // 4352 floats per buffer

// ---- scratch ----
__device__ float g_pp[3 * 2 * SEQ * DK];   // split-K proj partials (12 MB)
__device__ float g_qp[SEQ * DK];   // d-permuted within 8-col groups
__device__ float g_kp[SEQ * DK];   // d-permuted within 8-col groups
__device__ float g_vp[SEQ * DK];   // plain layout
__device__ float g_pO[NTA * MAXCH * BMA * DK];
__device__ float g_pm[NTA * MAXCH * BMA];
__device__ float g_pl[NTA * MAXCH * BMA];

__device__ __forceinline__ float f2tf(float f) {
    uint32_t u;
    asm("cvt.rn.tf32.f32 %0, %1;" : "=r"(u) : "f"(f));
    return __uint_as_float(u);
}

__device__ __forceinline__ void mma8(float& d0, float& d1, float& d2, float& d3,
                                     uint32_t a0, uint32_t a1, uint32_t a2, uint32_t a3,
                                     uint32_t b0, uint32_t b1)
{
    asm volatile(
        "mma.sync.aligned.m16n8k8.row.col.f32.tf32.tf32.f32 "
        "{%0,%1,%2,%3}, {%4,%5,%6,%7}, {%8,%9}, {%0,%1,%2,%3};\n"
        : "+f"(d0), "+f"(d1), "+f"(d2), "+f"(d3)
        : "r"(a0), "r"(a1), "r"(a2), "r"(a3), "r"(b0), "r"(b1));
}

__device__ __forceinline__ uint32_t ldu(const float* p)    { return __float_as_uint(*p); }
__device__ __forceinline__ uint32_t ldu_rn(const float* p) { return __float_as_uint(*p) + 0x1000u; }
__device__ __forceinline__ uint32_t fb(float f)            { return __float_as_uint(f); }

__device__ __forceinline__ void cp16(void* dst_smem, const void* src_gmem) {
    uint32_t d = (uint32_t)__cvta_generic_to_shared(dst_smem);
    asm volatile("cp.async.cg.shared.global [%0], [%1], 16;" :: "r"(d), "l"(src_gmem));
}
#define CP_COMMIT() asm volatile("cp.async.commit_group;")
#define CP_WAIT(n)  asm volatile("cp.async.wait_group %0;" :: "n"(n))

// ---------------------------------------------------------------------------
// Projection split-K partial: PP[which][kh] = X[:, kh*512:(kh+1)*512] @ W-half.
// 256 thr, tile 64x128, 2-stage cp.async (53 KB -> 3 blocks/SM; 384 blocks
// all co-resident). grid (64, 3, 2).
// ---------------------------------------------------------------------------
__global__ void __launch_bounds__(256, 3) proj_part_kernel(
    const float* __restrict__ q, const float* __restrict__ k, const float* __restrict__ v,
    const float* __restrict__ Wq, const float* __restrict__ Wk, const float* __restrict__ Wv)
{
    extern __shared__ float psm[];
    float* Xb = psm;                   // 2 x 64 x 36
    float* Wb = psm + 2 * PM * XP;     // 2 x 32 x 136

    const int which = blockIdx.y;
    const int kh    = blockIdx.z;
    const float* X = (which == 0) ? q  : (which == 1) ? k  : v;
    const float* W = (which == 0) ? Wq : (which == 1) ? Wk : Wv;
    float* OUT = g_pp + (size_t)(which * 2 + kh) * SEQ * DK;

    const int t    = threadIdx.x;
    const int warp = t >> 5;
    const int lane = t & 31;
    const int wr   = warp >> 2;
    const int wc   = warp & 3;
    const int g    = lane >> 2;
    const int tig  = lane & 3;
    const int r0   = blockIdx.x * PM;
    const int kbase = kh * KHALF * PKC;     // 0 or 512

    auto issue = [&](int kc) {
        const int k0 = kbase + kc * PKC;
        float* Xs = Xb + (kc & 1) * PM * XP;
        float* Ws = Wb + (kc & 1) * PKC * WP;
#pragma unroll
        for (int i = 0; i < 2; i++) {
            int idx = t + i * 256;
            int row = idx >> 3, c4 = idx & 7;
            cp16(&Xs[row * XP + c4 * 4], &X[(r0 + row) * DM + k0 + c4 * 4]);
        }
#pragma unroll
        for (int i = 0; i < 4; i++) {
            int idx = t + i * 256;
            int row = idx >> 5, c4 = idx & 31;
            cp16(&Ws[row * WP + c4 * 4], &W[(k0 + row) * DK + c4 * 4]);
        }
        CP_COMMIT();
    };

    float acc[8][4];
#pragma unroll
    for (int i = 0; i < 8; i++)
#pragma unroll
        for (int j = 0; j < 4; j++) acc[i][j] = 0.f;

    issue(0);
    issue(1);

    for (int kc = 0; kc < KHALF; kc++) {
        if (kc + 1 < KHALF) { CP_WAIT(1); } else { CP_WAIT(0); }
        __syncthreads();

        const float* Xs = Xb + (kc & 1) * PM * XP;
        const float* Ws = Wb + (kc & 1) * PKC * WP;

#pragma unroll
        for (int ks = 0; ks < 4; ks++) {
            const int kk = ks * 8;
            uint32_t a[2][4];
#pragma unroll
            for (int mf = 0; mf < 2; mf++) {
                const float* ab = &Xs[(wr * 32 + mf * 16 + g) * XP + kk + tig];
                a[mf][0] = ldu_rn(ab);
                a[mf][1] = ldu_rn(ab + 8 * XP);
                a[mf][2] = ldu_rn(ab + 4);
                a[mf][3] = ldu_rn(ab + 8 * XP + 4);
            }
            uint32_t b[4][2];
#pragma unroll
            for (int nf = 0; nf < 4; nf++) {
                b[nf][0] = ldu_rn(&Ws[(kk + tig) * WP + wc * 32 + nf * 8 + g]);
                b[nf][1] = ldu_rn(&Ws[(kk + tig + 4) * WP + wc * 32 + nf * 8 + g]);
            }
#pragma unroll
            for (int mf = 0; mf < 2; mf++)
#pragma unroll
                for (int nf = 0; nf < 4; nf++)
                    mma8(acc[mf * 4 + nf][0], acc[mf * 4 + nf][1],
                         acc[mf * 4 + nf][2], acc[mf * 4 + nf][3],
                         a[mf][0], a[mf][1], a[mf][2], a[mf][3],
                         b[nf][0], b[nf][1]);
        }

        __syncthreads();
        if (kc + 2 < KHALF) issue(kc + 2);
    }

    // epilogue: raw fp32 partials, plain layout, float2
#pragma unroll
    for (int mf = 0; mf < 2; mf++) {
        const int row0 = r0 + wr * 32 + mf * 16 + g;
        const int row1 = row0 + 8;
#pragma unroll
        for (int nf = 0; nf < 4; nf++) {
            int col = wc * 32 + nf * 8 + 2 * tig;
            float2 o0, o1;
            o0.x = acc[mf * 4 + nf][0]; o0.y = acc[mf * 4 + nf][1];
            o1.x = acc[mf * 4 + nf][2]; o1.y = acc[mf * 4 + nf][3];
            *reinterpret_cast<float2*>(&OUT[row0 * DK + col]) = o0;
            *reinterpret_cast<float2*>(&OUT[row1 * DK + col]) = o1;
        }
    }
}

// ---------------------------------------------------------------------------
// Proj reduce: OUT = round_tf32((P0 + P1 + b) * osc), with d-permutation for
// q/k. grid (128, 3), 256 thr, 32 rows per block.
// ---------------------------------------------------------------------------
__global__ void __launch_bounds__(256) proj_reduce_kernel(
    const float* __restrict__ bq, const float* __restrict__ bk, const float* __restrict__ bv)
{
    const int which = blockIdx.y;
    const float* B = (which == 0) ? bq : (which == 1) ? bk : bv;
    const float* P0 = g_pp + (size_t)(which * 2 + 0) * SEQ * DK;
    const float* P1 = g_pp + (size_t)(which * 2 + 1) * SEQ * DK;
    float* OUT = (which == 0) ? g_qp : (which == 1) ? g_kp : g_vp;
    const float osc = (which == 0) ? 0.08838834764831845f : 1.0f;

    const int t  = threadIdx.x;
    const int r0 = blockIdx.x * 32;

#pragma unroll
    for (int i = 0; i < 16; i++) {
        int idx = t + i * 256;            // < 4096 = 32 rows x 128 cols
        int row = r0 + (idx >> 7);
        int col = idx & 127;
        float val = P0[row * DK + col] + P1[row * DK + col] + B[col];
        val = f2tf(val * osc);
        if (which == 2) {
            OUT[row * DK + col] = val;
        } else {
            int j = col & 7;
            int pcol = (col & ~7) | (2 * (j & 3) + (j >> 2));
            OUT[row * DK + pcol] = val;
        }
    }
}

// ---------------------------------------------------------------------------
// Split-KV causal flash attention partials (exact R12 / best version).
// 128 thr, 2 blocks/SM, 3-stage cp.async, separate P buffer, Q frags in regs.
// ---------------------------------------------------------------------------
__global__ void __launch_bounds__(128, 2) attn_part_kernel()
{
    extern __shared__ float sm[];
    float* Kb = sm;                 // 3 x 32 x 136
    float* Vb = sm + 3 * KST;       // 3 x 32 x 136
    float* Ps = sm + 6 * KST;       // 4 x 16 x 36

    const int t    = threadIdx.x;
    const int warp = t >> 5;
    const int lane = t & 31;
    const int g    = lane >> 2;
    const int tig  = lane & 3;
    float* Pw = Ps + warp * (16 * PP);

    // heavy-first decode: tile r has (r/8)+1 chunks
    int Bd = ABLOCKS - 1 - (int)blockIdx.x;
    int tier = 1, rem = Bd;
    while (rem >= 8 * tier) { rem -= 8 * tier; tier++; }
    const int r = (tier - 1) * 8 + rem / tier;
    const int c = rem % tier;

    const int rbase  = r * BMA;
    const int c0base = c * CHUNK;
    const int colend = min(c0base + CHUNK, rbase + BMA);
    const int nct    = (colend - c0base) / BNA;   // >= 2 always

    auto issue_kv = [&](int tc) {
        const int c0 = c0base + tc * BNA;
        float* Kd = Kb + (tc % 3) * KST;
        float* Vd = Vb + ((tc + 2) % 3) * KST;
#pragma unroll
        for (int i = 0; i < 8; i++) {
            int idx = t + i * 128;
            int row = idx >> 5, c4 = idx & 31;
            cp16(&Kd[row * KP + c4 * 4], &g_kp[(c0 + row) * DK + c4 * 4]);
            cp16(&Vd[row * KP + c4 * 4], &g_vp[(c0 + row) * DK + c4 * 4]);
        }
        CP_COMMIT();
    };

    // group 1: Q -> V buffers 0,1 (64 rows)
#pragma unroll
    for (int i = 0; i < 16; i++) {
        int idx = t + i * 128;
        int row = idx >> 5, c4 = idx & 31;
        cp16(&Vb[(row >> 5) * KST + (row & 31) * KP + c4 * 4],
             &g_qp[(rbase + row) * DK + c4 * 4]);
    }
    CP_COMMIT();
    // group 2: tile 0 -> K0, V2
    issue_kv(0);
    CP_WAIT(1);           // Q landed
    __syncthreads();

    // cache Q A-fragments (permuted layout -> float2)
    uint32_t qf[16][4];
    {
        const float* Qsrc = Vb + (warp >> 1) * KST;
        const int row_l = (warp & 1) * 16 + g;
#pragma unroll
        for (int ks = 0; ks < 16; ks++) {
            float2 qa = *reinterpret_cast<const float2*>(&Qsrc[row_l * KP + ks * 8 + 2 * tig]);
            float2 qb = *reinterpret_cast<const float2*>(&Qsrc[(row_l + 8) * KP + ks * 8 + 2 * tig]);
            qf[ks][0] = fb(qa.x);
            qf[ks][1] = fb(qb.x);
            qf[ks][2] = fb(qa.y);
            qf[ks][3] = fb(qb.y);
        }
    }
    __syncthreads();      // V0/V1 free
    issue_kv(1);          // tile 1 -> K1, V0

    float o[16][4];
#pragma unroll
    for (int nt = 0; nt < 16; nt++)
#pragma unroll
        for (int j = 0; j < 4; j++) o[nt][j] = 0.f;

    float m0 = -1e30f, m1 = -1e30f, l0 = 0.f, l1 = 0.f;
    const int grow0 = rbase + warp * 16 + g;
    const int grow1 = grow0 + 8;

    for (int tc = 0; tc < nct; tc++) {
        const int c0 = c0base + tc * BNA;
        if (tc + 1 < nct) { CP_WAIT(1); } else { CP_WAIT(0); }
        __syncthreads();
        if (tc + 2 < nct) issue_kv(tc + 2);

        const float* Ks = Kb + (tc % 3) * KST;
        const float* Vs = Vb + ((tc + 2) % 3) * KST;

        // ---- S = Q K^T ----
        float s[4][4];
#pragma unroll
        for (int nt = 0; nt < 4; nt++)
#pragma unroll
            for (int j = 0; j < 4; j++) s[nt][j] = 0.f;

#pragma unroll
        for (int ks = 0; ks < 16; ks++) {
            const int kk = ks * 8;
#pragma unroll
            for (int nt = 0; nt < 4; nt++) {
                float2 kv = *reinterpret_cast<const float2*>(&Ks[(nt * 8 + g) * KP + kk + 2 * tig]);
                mma8(s[nt][0], s[nt][1], s[nt][2], s[nt][3],
                     qf[ks][0], qf[ks][1], qf[ks][2], qf[ks][3],
                     fb(kv.x), fb(kv.y));
            }
        }

        // ---- causal mask + online softmax ----
        float mloc0 = -1e30f, mloc1 = -1e30f;
#pragma unroll
        for (int nt = 0; nt < 4; nt++) {
            int colb = c0 + nt * 8 + 2 * tig;
            float x0 = (colb     <= grow0) ? s[nt][0] : -1e30f;
            float x1 = (colb + 1 <= grow0) ? s[nt][1] : -1e30f;
            float x2 = (colb     <= grow1) ? s[nt][2] : -1e30f;
            float x3 = (colb + 1 <= grow1) ? s[nt][3] : -1e30f;
            s[nt][0] = x0; s[nt][1] = x1; s[nt][2] = x2; s[nt][3] = x3;
            mloc0 = fmaxf(mloc0, fmaxf(x0, x1));
            mloc1 = fmaxf(mloc1, fmaxf(x2, x3));
        }
        mloc0 = fmaxf(mloc0, __shfl_xor_sync(0xffffffffu, mloc0, 1));
        mloc0 = fmaxf(mloc0, __shfl_xor_sync(0xffffffffu, mloc0, 2));
        mloc1 = fmaxf(mloc1, __shfl_xor_sync(0xffffffffu, mloc1, 1));
        mloc1 = fmaxf(mloc1, __shfl_xor_sync(0xffffffffu, mloc1, 2));

        float mn0 = fmaxf(m0, mloc0);
        float mn1 = fmaxf(m1, mloc1);
        float sc0 = __expf(m0 - mn0);
        float sc1 = __expf(m1 - mn1);

        float ps0 = 0.f, ps1 = 0.f;
#pragma unroll
        for (int nt = 0; nt < 4; nt++) {
            float p0 = __expf(s[nt][0] - mn0);
            float p1 = __expf(s[nt][1] - mn0);
            float p2 = __expf(s[nt][2] - mn1);
            float p3 = __expf(s[nt][3] - mn1);
            ps0 += p0 + p1;
            ps1 += p2 + p3;
            float* d0 = &Pw[g * PP + nt * 8 + 2 * tig];
            d0[0] = f2tf(p0); d0[1] = f2tf(p1);
            float* d1 = &Pw[(g + 8) * PP + nt * 8 + 2 * tig];
            d1[0] = f2tf(p2); d1[1] = f2tf(p3);
        }
        ps0 += __shfl_xor_sync(0xffffffffu, ps0, 1);
        ps0 += __shfl_xor_sync(0xffffffffu, ps0, 2);
        ps1 += __shfl_xor_sync(0xffffffffu, ps1, 1);
        ps1 += __shfl_xor_sync(0xffffffffu, ps1, 2);

        l0 = l0 * sc0 + ps0;  m0 = mn0;
        l1 = l1 * sc1 + ps1;  m1 = mn1;

        __syncwarp();

        // ---- rescale O, then O += P @ V ----
#pragma unroll
        for (int nt = 0; nt < 16; nt++) {
            o[nt][0] *= sc0; o[nt][1] *= sc0;
            o[nt][2] *= sc1; o[nt][3] *= sc1;
        }

#pragma unroll
        for (int ks = 0; ks < 4; ks++) {
            const int kk = ks * 8;
            const float* ab = &Pw[g * PP + kk + tig];
            uint32_t a0 = ldu(ab);
            uint32_t a1 = ldu(ab + 8 * PP);
            uint32_t a2 = ldu(ab + 4);
            uint32_t a3 = ldu(ab + 8 * PP + 4);
#pragma unroll
            for (int nt = 0; nt < 16; nt++) {
                uint32_t b0 = ldu(&Vs[(kk + tig) * KP + nt * 8 + g]);
                uint32_t b1 = ldu(&Vs[(kk + tig + 4) * KP + nt * 8 + g]);
                mma8(o[nt][0], o[nt][1], o[nt][2], o[nt][3], a0, a1, a2, a3, b0, b1);
            }
        }
    }

    // ---- write unnormalized partials ----
    const int pidx = r * MAXCH + c;
    float* baseO = &g_pO[(size_t)pidx * BMA * DK];
    const int row0 = warp * 16 + g;
    const int row1 = row0 + 8;
#pragma unroll
    for (int nt = 0; nt < 16; nt++) {
        int col = nt * 8 + 2 * tig;
        float2 w0; w0.x = o[nt][0]; w0.y = o[nt][1];
        float2 w1; w1.x = o[nt][2]; w1.y = o[nt][3];
        *reinterpret_cast<float2*>(&baseO[row0 * DK + col]) = w0;
        *reinterpret_cast<float2*>(&baseO[row1 * DK + col]) = w1;
    }
    if (tig == 0) {
        g_pm[pidx * BMA + row0] = m0;
        g_pm[pidx * BMA + row1] = m1;
        g_pl[pidx * BMA + row0] = l0;
        g_pl[pidx * BMA + row1] = l1;
    }
}

// ---------------------------------------------------------------------------
// Merge: 1024 blocks, block (r, part) does 4 rows x 128 d (1 float4/thread).
// ---------------------------------------------------------------------------
__global__ void __launch_bounds__(128) merge_kernel(float* __restrict__ out)
{
    __shared__ float s_m[4 * MAXCH];
    __shared__ float s_l[4 * MAXCH];
    __shared__ float s_w[4 * MAXCH];
    __shared__ float s_inv[4];

    const int r    = blockIdx.x >> 4;
    const int part = blockIdx.x & 15;
    const int nch  = (r >> 3) + 1;
    const int t    = threadIdx.x;

    if (t < 32) {
        int row4 = t >> 3, ch = t & 7;
        if (ch < nch) {
            s_m[t] = g_pm[(r * MAXCH + ch) * BMA + part * 4 + row4];
            s_l[t] = g_pl[(r * MAXCH + ch) * BMA + part * 4 + row4];
        } else {
            s_m[t] = -1e30f; s_l[t] = 0.f;
        }
    }
    __syncthreads();

    if (t < 4) {
        float mx = -1e30f;
#pragma unroll
        for (int ch = 0; ch < MAXCH; ch++) mx = fmaxf(mx, s_m[t * 8 + ch]);
        float den = 0.f;
#pragma unroll
        for (int ch = 0; ch < MAXCH; ch++) {
            float w = __expf(s_m[t * 8 + ch] - mx);
            s_w[t * 8 + ch] = w;
            den += w * s_l[t * 8 + ch];
        }
        s_inv[t] = 1.f / den;
    }
    __syncthreads();

    {
        int row4 = t >> 5, d4 = t & 31;          // 128 = 4 rows x 32 float4
        int growl = part * 4 + row4;
        float4 acc; acc.x = acc.y = acc.z = acc.w = 0.f;
#pragma unroll
        for (int ch = 0; ch < MAXCH; ch++) {
            if (ch < nch) {
                float4 p = reinterpret_cast<const float4*>(
                    &g_pO[((size_t)(r * MAXCH + ch) * BMA + growl) * DK])[d4];
                float w = s_w[row4 * 8 + ch];
                acc.x += w * p.x; acc.y += w * p.y;
                acc.z += w * p.z; acc.w += w * p.w;
            }
        }
        float inv = s_inv[row4];
        acc.x *= inv; acc.y *= inv; acc.z *= inv; acc.w *= inv;
        reinterpret_cast<float4*>(&out[(r * BMA + growl) * DK])[d4] = acc;
    }
}

// ---------------------------------------------------------------------------
extern "C" void kernel_launch(void* const* d_in, const int* in_sizes, int n_in,
                              void* d_out, int out_size)
{
    const float* q  = (const float*)d_in[0];
    const float* k  = (const float*)d_in[1];
    const float* v  = (const float*)d_in[2];
    const float* Wq = (const float*)d_in[3];
    const float* bq = (const float*)d_in[4];
    const float* Wk = (const float*)d_in[5];
    const float* bk = (const float*)d_in[6];
    const float* Wv = (const float*)d_in[7];
    const float* bv = (const float*)d_in[8];
    float* out = (float*)d_out;

    const int smem_proj = 2 * (PM * XP + PKC * WP) * sizeof(float);        // 53248 -> 3/SM
    const int smem_attn = (6 * KST + 4 * 16 * PP) * sizeof(float);         // 113664
    cudaFuncSetAttribute(proj_part_kernel, cudaFuncAttributeMaxDynamicSharedMemorySize, smem_proj);
    cudaFuncSetAttribute(attn_part_kernel, cudaFuncAttributeMaxDynamicSharedMemorySize, smem_attn);

    proj_part_kernel<<<dim3(SEQ / PM, 3, 2), 256, smem_proj>>>(q, k, v, Wq, Wk, Wv);
    proj_reduce_kernel<<<dim3(SEQ / 32, 3), 256>>>(bq, bk, bv);
    attn_part_kernel<<<ABLOCKS, 128, smem_attn>>>();
    merge_kernel<<<NTA * 16, 128>>>(out);
}

// round 16
// speedup vs baseline: 1.1515x; 1.0093x over previous
#include <cuda_runtime.h>
#include <math.h>
#include <stdint.h>

#define SEQ 4096
#define DM  1024
#define DK  128

// ---- proj tiling: split-K (2 halves), 64x128 tiles, 2-stage pipeline ----
#define PM   64
#define PKC  32
#define KHALF 16          // chunks per k-half (16 * 32 = 512)
#define XP   36           // Xs stride
#define WP   136          // Ws stride (mod 32 = 8)

// ---- attention tiling (R12 known-good) ----
#define BMA   64
#define BNA   32
#define CHUNK 512
#define NTA   (SEQ / BMA)
#define MAXCH 8
#define ABLOCKS 288       // sum_{tier=1..8} 8*tier
#define KP  136           // K/V smem stride (mod 32 = 8: LDS.64 conflict-free)
#define PP  36
#define KST (32 * KP)     // 4352 floats per buffer

// ---- scratch ----
__device__ float g_pp[3 * 2 * SEQ * DK];   // split-K proj partials (12 MB)
__device__ float g_qp[SEQ * DK];   // d-permuted within 8-col groups
__device__ float g_kp[SEQ * DK];   // d-permuted within 8-col groups
__device__ float g_vp[SEQ * DK];   // plain layout
__device__ float g_pO[NTA * MAXCH * BMA * DK];
__device__ float g_pm[NTA * MAXCH * BMA];
__device__ float g_pl[NTA * MAXCH * BMA];

__device__ __forceinline__ float f2tf(float f) {
    uint32_t u;
    asm("cvt.rn.tf32.f32 %0, %1;" : "=r"(u) : "f"(f));
    return __uint_as_float(u);
}

__device__ __forceinline__ void mma8(float& d0, float& d1, float& d2, float& d3,
                                     uint32_t a0, uint32_t a1, uint32_t a2, uint32_t a3,
                                     uint32_t b0, uint32_t b1)
{
    asm volatile(
        "mma.sync.aligned.m16n8k8.row.col.f32.tf32.tf32.f32 "
        "{%0,%1,%2,%3}, {%4,%5,%6,%7}, {%8,%9}, {%0,%1,%2,%3};\n"
        : "+f"(d0), "+f"(d1), "+f"(d2), "+f"(d3)
        : "r"(a0), "r"(a1), "r"(a2), "r"(a3), "r"(b0), "r"(b1));
}

__device__ __forceinline__ uint32_t ldu(const float* p)    { return __float_as_uint(*p); }
__device__ __forceinline__ uint32_t ldu_rn(const float* p) { return __float_as_uint(*p) + 0x1000u; }
__device__ __forceinline__ uint32_t fb(float f)            { return __float_as_uint(f); }

__device__ __forceinline__ void cp16(void* dst_smem, const void* src_gmem) {
    uint32_t d = (uint32_t)__cvta_generic_to_shared(dst_smem);
    asm volatile("cp.async.cg.shared.global [%0], [%1], 16;" :: "r"(d), "l"(src_gmem));
}
#define CP_COMMIT() asm volatile("cp.async.commit_group;")
#define CP_WAIT(n)  asm volatile("cp.async.wait_group %0;" :: "n"(n))

// ---------------------------------------------------------------------------
// Projection split-K partial (exact R15): PP[which][kh] = X-half @ W-half.
// 256 thr, tile 64x128, 2-stage cp.async, grid (64, 3, 2) all co-resident.
// ---------------------------------------------------------------------------
__global__ void __launch_bounds__(256, 3) proj_part_kernel(
    const float* __restrict__ q, const float* __restrict__ k, const float* __restrict__ v,
    const float* __restrict__ Wq, const float* __restrict__ Wk, const float* __restrict__ Wv)
{
    extern __shared__ float psm[];
    float* Xb = psm;                   // 2 x 64 x 36
    float* Wb = psm + 2 * PM * XP;     // 2 x 32 x 136

    const int which = blockIdx.y;
    const int kh    = blockIdx.z;
    const float* X = (which == 0) ? q  : (which == 1) ? k  : v;
    const float* W = (which == 0) ? Wq : (which == 1) ? Wk : Wv;
    float* OUT = g_pp + (size_t)(which * 2 + kh) * SEQ * DK;

    const int t    = threadIdx.x;
    const int warp = t >> 5;
    const int lane = t & 31;
    const int wr   = warp >> 2;
    const int wc   = warp & 3;
    const int g    = lane >> 2;
    const int tig  = lane & 3;
    const int r0   = blockIdx.x * PM;
    const int kbase = kh * KHALF * PKC;     // 0 or 512

    auto issue = [&](int kc) {
        const int k0 = kbase + kc * PKC;
        float* Xs = Xb + (kc & 1) * PM * XP;
        float* Ws = Wb + (kc & 1) * PKC * WP;
#pragma unroll
        for (int i = 0; i < 2; i++) {
            int idx = t + i * 256;
            int row = idx >> 3, c4 = idx & 7;
            cp16(&Xs[row * XP + c4 * 4], &X[(r0 + row) * DM + k0 + c4 * 4]);
        }
#pragma unroll
        for (int i = 0; i < 4; i++) {
            int idx = t + i * 256;
            int row = idx >> 5, c4 = idx & 31;
            cp16(&Ws[row * WP + c4 * 4], &W[(k0 + row) * DK + c4 * 4]);
        }
        CP_COMMIT();
    };

    float acc[8][4];
#pragma unroll
    for (int i = 0; i < 8; i++)
#pragma unroll
        for (int j = 0; j < 4; j++) acc[i][j] = 0.f;

    issue(0);
    issue(1);

    for (int kc = 0; kc < KHALF; kc++) {
        if (kc + 1 < KHALF) { CP_WAIT(1); } else { CP_WAIT(0); }
        __syncthreads();

        const float* Xs = Xb + (kc & 1) * PM * XP;
        const float* Ws = Wb + (kc & 1) * PKC * WP;

#pragma unroll
        for (int ks = 0; ks < 4; ks++) {
            const int kk = ks * 8;
            uint32_t a[2][4];
#pragma unroll
            for (int mf = 0; mf < 2; mf++) {
                const float* ab = &Xs[(wr * 32 + mf * 16 + g) * XP + kk + tig];
                a[mf][0] = ldu_rn(ab);
                a[mf][1] = ldu_rn(ab + 8 * XP);
                a[mf][2] = ldu_rn(ab + 4);
                a[mf][3] = ldu_rn(ab + 8 * XP + 4);
            }
            uint32_t b[4][2];
#pragma unroll
            for (int nf = 0; nf < 4; nf++) {
                b[nf][0] = ldu_rn(&Ws[(kk + tig) * WP + wc * 32 + nf * 8 + g]);
                b[nf][1] = ldu_rn(&Ws[(kk + tig + 4) * WP + wc * 32 + nf * 8 + g]);
            }
#pragma unroll
            for (int mf = 0; mf < 2; mf++)
#pragma unroll
                for (int nf = 0; nf < 4; nf++)
                    mma8(acc[mf * 4 + nf][0], acc[mf * 4 + nf][1],
                         acc[mf * 4 + nf][2], acc[mf * 4 + nf][3],
                         a[mf][0], a[mf][1], a[mf][2], a[mf][3],
                         b[nf][0], b[nf][1]);
        }

        __syncthreads();
        if (kc + 2 < KHALF) issue(kc + 2);
    }

    // epilogue: raw fp32 partials, plain layout, float2
#pragma unroll
    for (int mf = 0; mf < 2; mf++) {
        const int row0 = r0 + wr * 32 + mf * 16 + g;
        const int row1 = row0 + 8;
#pragma unroll
        for (int nf = 0; nf < 4; nf++) {
            int col = wc * 32 + nf * 8 + 2 * tig;
            float2 o0, o1;
            o0.x = acc[mf * 4 + nf][0]; o0.y = acc[mf * 4 + nf][1];
            o1.x = acc[mf * 4 + nf][2]; o1.y = acc[mf * 4 + nf][3];
            *reinterpret_cast<float2*>(&OUT[row0 * DK + col]) = o0;
            *reinterpret_cast<float2*>(&OUT[row1 * DK + col]) = o1;
        }
    }
}

// ---------------------------------------------------------------------------
// Proj reduce (exact R15): OUT = round_tf32((P0 + P1 + b) * osc), d-permuted
// for q/k. grid (128, 3), 256 thr.
// ---------------------------------------------------------------------------
__global__ void __launch_bounds__(256) proj_reduce_kernel(
    const float* __restrict__ bq, const float* __restrict__ bk, const float* __restrict__ bv)
{
    const int which = blockIdx.y;
    const float* B = (which == 0) ? bq : (which == 1) ? bk : bv;
    const float* P0 = g_pp + (size_t)(which * 2 + 0) * SEQ * DK;
    const float* P1 = g_pp + (size_t)(which * 2 + 1) * SEQ * DK;
    float* OUT = (which == 0) ? g_qp : (which == 1) ? g_kp : g_vp;
    const float osc = (which == 0) ? 0.08838834764831845f : 1.0f;

    const int t  = threadIdx.x;
    const int r0 = blockIdx.x * 32;

#pragma unroll
    for (int i = 0; i < 16; i++) {
        int idx = t + i * 256;            // < 4096 = 32 rows x 128 cols
        int row = r0 + (idx >> 7);
        int col = idx & 127;
        float val = P0[row * DK + col] + P1[row * DK + col] + B[col];
        val = f2tf(val * osc);
        if (which == 2) {
            OUT[row * DK + col] = val;
        } else {
            int j = col & 7;
            int pcol = (col & ~7) | (2 * (j & 3) + (j >> 2));
            OUT[row * DK + pcol] = val;
        }
    }
}

// ---------------------------------------------------------------------------
// Split-KV causal flash attention partials (R12 core). nch==1 tiles (r<8)
// write normalized output directly; others write unnormalized partials.
// ---------------------------------------------------------------------------
__global__ void __launch_bounds__(128, 2) attn_part_kernel(float* __restrict__ out)
{
    extern __shared__ float sm[];
    float* Kb = sm;                 // 3 x 32 x 136
    float* Vb = sm + 3 * KST;       // 3 x 32 x 136
    float* Ps = sm + 6 * KST;       // 4 x 16 x 36

    const int t    = threadIdx.x;
    const int warp = t >> 5;
    const int lane = t & 31;
    const int g    = lane >> 2;
    const int tig  = lane & 3;
    float* Pw = Ps + warp * (16 * PP);

    // heavy-first decode: tile r has (r/8)+1 chunks
    int Bd = ABLOCKS - 1 - (int)blockIdx.x;
    int tier = 1, rem = Bd;
    while (rem >= 8 * tier) { rem -= 8 * tier; tier++; }
    const int r = (tier - 1) * 8 + rem / tier;
    const int c = rem % tier;

    const int rbase  = r * BMA;
    const int c0base = c * CHUNK;
    const int colend = min(c0base + CHUNK, rbase + BMA);
    const int nct    = (colend - c0base) / BNA;   // >= 2 always
    const int nch    = (r >> 3) + 1;

    auto issue_kv = [&](int tc) {
        const int c0 = c0base + tc * BNA;
        float* Kd = Kb + (tc % 3) * KST;
        float* Vd = Vb + ((tc + 2) % 3) * KST;
#pragma unroll
        for (int i = 0; i < 8; i++) {
            int idx = t + i * 128;
            int row = idx >> 5, c4 = idx & 31;
            cp16(&Kd[row * KP + c4 * 4], &g_kp[(c0 + row) * DK + c4 * 4]);
            cp16(&Vd[row * KP + c4 * 4], &g_vp[(c0 + row) * DK + c4 * 4]);
        }
        CP_COMMIT();
    };

    // group 1: Q -> V buffers 0,1 (64 rows)
#pragma unroll
    for (int i = 0; i < 16; i++) {
        int idx = t + i * 128;
        int row = idx >> 5, c4 = idx & 31;
        cp16(&Vb[(row >> 5) * KST + (row & 31) * KP + c4 * 4],
             &g_qp[(rbase + row) * DK + c4 * 4]);
    }
    CP_COMMIT();
    // group 2: tile 0 -> K0, V2
    issue_kv(0);
    CP_WAIT(1);           // Q landed
    __syncthreads();

    // cache Q A-fragments (permuted layout -> float2)
    uint32_t qf[16][4];
    {
        const float* Qsrc = Vb + (warp >> 1) * KST;
        const int row_l = (warp & 1) * 16 + g;
#pragma unroll
        for (int ks = 0; ks < 16; ks++) {
            float2 qa = *reinterpret_cast<const float2*>(&Qsrc[row_l * KP + ks * 8 + 2 * tig]);
            float2 qb = *reinterpret_cast<const float2*>(&Qsrc[(row_l + 8) * KP + ks * 8 + 2 * tig]);
            qf[ks][0] = fb(qa.x);
            qf[ks][1] = fb(qb.x);
            qf[ks][2] = fb(qa.y);
            qf[ks][3] = fb(qb.y);
        }
    }
    __syncthreads();      // V0/V1 free
    issue_kv(1);          // tile 1 -> K1, V0

    float o[16][4];
#pragma unroll
    for (int nt = 0; nt < 16; nt++)
#pragma unroll
        for (int j = 0; j < 4; j++) o[nt][j] = 0.f;

    float m0 = -1e30f, m1 = -1e30f, l0 = 0.f, l1 = 0.f;
    const int grow0 = rbase + warp * 16 + g;
    const int grow1 = grow0 + 8;

    for (int tc = 0; tc < nct; tc++) {
        const int c0 = c0base + tc * BNA;
        if (tc + 1 < nct) { CP_WAIT(1); } else { CP_WAIT(0); }
        __syncthreads();
        if (tc + 2 < nct) issue_kv(tc + 2);

        const float* Ks = Kb + (tc % 3) * KST;
        const float* Vs = Vb + ((tc + 2) % 3) * KST;

        // ---- S = Q K^T ----
        float s[4][4];
#pragma unroll
        for (int nt = 0; nt < 4; nt++)
#pragma unroll
            for (int j = 0; j < 4; j++) s[nt][j] = 0.f;

#pragma unroll
        for (int ks = 0; ks < 16; ks++) {
            const int kk = ks * 8;
#pragma unroll
            for (int nt = 0; nt < 4; nt++) {
                float2 kv = *reinterpret_cast<const float2*>(&Ks[(nt * 8 + g) * KP + kk + 2 * tig]);
                mma8(s[nt][0], s[nt][1], s[nt][2], s[nt][3],
                     qf[ks][0], qf[ks][1], qf[ks][2], qf[ks][3],
                     fb(kv.x), fb(kv.y));
            }
        }

        // ---- causal mask + online softmax ----
        float mloc0 = -1e30f, mloc1 = -1e30f;
#pragma unroll
        for (int nt = 0; nt < 4; nt++) {
            int colb = c0 + nt * 8 + 2 * tig;
            float x0 = (colb     <= grow0) ? s[nt][0] : -1e30f;
            float x1 = (colb + 1 <= grow0) ? s[nt][1] : -1e30f;
            float x2 = (colb     <= grow1) ? s[nt][2] : -1e30f;
            float x3 = (colb + 1 <= grow1) ? s[nt][3] : -1e30f;
            s[nt][0] = x0; s[nt][1] = x1; s[nt][2] = x2; s[nt][3] = x3;
            mloc0 = fmaxf(mloc0, fmaxf(x0, x1));
            mloc1 = fmaxf(mloc1, fmaxf(x2, x3));
        }
        mloc0 = fmaxf(mloc0, __shfl_xor_sync(0xffffffffu, mloc0, 1));
        mloc0 = fmaxf(mloc0, __shfl_xor_sync(0xffffffffu, mloc0, 2));
        mloc1 = fmaxf(mloc1, __shfl_xor_sync(0xffffffffu, mloc1, 1));
        mloc1 = fmaxf(mloc1, __shfl_xor_sync(0xffffffffu, mloc1, 2));

        float mn0 = fmaxf(m0, mloc0);
        float mn1 = fmaxf(m1, mloc1);
        float sc0 = __expf(m0 - mn0);
        float sc1 = __expf(m1 - mn1);

        float ps0 = 0.f, ps1 = 0.f;
#pragma unroll
        for (int nt = 0; nt < 4; nt++) {
            float p0 = __expf(s[nt][0] - mn0);
            float p1 = __expf(s[nt][1] - mn0);
            float p2 = __expf(s[nt][2] - mn1);
            float p3 = __expf(s[nt][3] - mn1);
            ps0 += p0 + p1;
            ps1 += p2 + p3;
            float* d0 = &Pw[g * PP + nt * 8 + 2 * tig];
            d0[0] = f2tf(p0); d0[1] = f2tf(p1);
            float* d1 = &Pw[(g + 8) * PP + nt * 8 + 2 * tig];
            d1[0] = f2tf(p2); d1[1] = f2tf(p3);
        }
        ps0 += __shfl_xor_sync(0xffffffffu, ps0, 1);
        ps0 += __shfl_xor_sync(0xffffffffu, ps0, 2);
        ps1 += __shfl_xor_sync(0xffffffffu, ps1, 1);
        ps1 += __shfl_xor_sync(0xffffffffu, ps1, 2);

        l0 = l0 * sc0 + ps0;  m0 = mn0;
        l1 = l1 * sc1 + ps1;  m1 = mn1;

        __syncwarp();

        // ---- rescale O, then O += P @ V ----
#pragma unroll
        for (int nt = 0; nt < 16; nt++) {
            o[nt][0] *= sc0; o[nt][1] *= sc0;
            o[nt][2] *= sc1; o[nt][3] *= sc1;
        }

#pragma unroll
        for (int ks = 0; ks < 4; ks++) {
            const int kk = ks * 8;
            const float* ab = &Pw[g * PP + kk + tig];
            uint32_t a0 = ldu(ab);
            uint32_t a1 = ldu(ab + 8 * PP);
            uint32_t a2 = ldu(ab + 4);
            uint32_t a3 = ldu(ab + 8 * PP + 4);
#pragma unroll
            for (int nt = 0; nt < 16; nt++) {
                uint32_t b0 = ldu(&Vs[(kk + tig) * KP + nt * 8 + g]);
                uint32_t b1 = ldu(&Vs[(kk + tig + 4) * KP + nt * 8 + g]);
                mma8(o[nt][0], o[nt][1], o[nt][2], o[nt][3], a0, a1, a2, a3, b0, b1);
            }
        }
    }

    const int row0 = warp * 16 + g;
    const int row1 = row0 + 8;

    // ---- single-chunk tiles (r<8): write normalized output directly ----
    if (nch == 1) {
        float inv0 = 1.f / l0;
        float inv1 = 1.f / l1;
#pragma unroll
        for (int nt = 0; nt < 16; nt++) {
            int col = nt * 8 + 2 * tig;
            float2 w0; w0.x = o[nt][0] * inv0; w0.y = o[nt][1] * inv0;
            float2 w1; w1.x = o[nt][2] * inv1; w1.y = o[nt][3] * inv1;
            *reinterpret_cast<float2*>(&out[(rbase + row0) * DK + col]) = w0;
            *reinterpret_cast<float2*>(&out[(rbase + row1) * DK + col]) = w1;
        }
        return;
    }

    // ---- write unnormalized partials ----
    const int pidx = r * MAXCH + c;
    float* baseO = &g_pO[(size_t)pidx * BMA * DK];
#pragma unroll
    for (int nt = 0; nt < 16; nt++) {
        int col = nt * 8 + 2 * tig;
        float2 w0; w0.x = o[nt][0]; w0.y = o[nt][1];
        float2 w1; w1.x = o[nt][2]; w1.y = o[nt][3];
        *reinterpret_cast<float2*>(&baseO[row0 * DK + col]) = w0;
        *reinterpret_cast<float2*>(&baseO[row1 * DK + col]) = w1;
    }
    if (tig == 0) {
        g_pm[pidx * BMA + row0] = m0;
        g_pm[pidx * BMA + row1] = m1;
        g_pl[pidx * BMA + row0] = l0;
        g_pl[pidx * BMA + row1] = l1;
    }
}

// ---------------------------------------------------------------------------
// Merge: tiles r in [8, 64) only. 1792 blocks, block (r, part) does
// 2 rows x 128 d, float2 per thread -> ~48 warps/SM for latency hiding.
// ---------------------------------------------------------------------------
__global__ void __launch_bounds__(128) merge_kernel(float* __restrict__ out)
{
    __shared__ float s_w[2 * MAXCH];
    __shared__ float s_inv[2];

    const int r    = 8 + (blockIdx.x >> 5);   // 8..63
    const int part = blockIdx.x & 31;         // 0..31 (2 rows each)
    const int nch  = (r >> 3) + 1;            // 2..8
    const int t    = threadIdx.x;

    if (t < 16) {
        int row2 = t >> 3, ch = t & 7;
        float mv = -1e30f, lv = 0.f;
        if (ch < nch) {
            mv = g_pm[(r * MAXCH + ch) * BMA + part * 2 + row2];
            lv = g_pl[(r * MAXCH + ch) * BMA + part * 2 + row2];
        }
        // 8-lane reductions within the half-row group
        float mx = mv;
        mx = fmaxf(mx, __shfl_xor_sync(0x0000ffffu, mx, 4));
        mx = fmaxf(mx, __shfl_xor_sync(0x0000ffffu, mx, 2));
        mx = fmaxf(mx, __shfl_xor_sync(0x0000ffffu, mx, 1));
        float w = (ch < nch) ? __expf(mv - mx) : 0.f;
        float den = w * lv;
        den += __shfl_xor_sync(0x0000ffffu, den, 4);
        den += __shfl_xor_sync(0x0000ffffu, den, 2);
        den += __shfl_xor_sync(0x0000ffffu, den, 1);
        s_w[t] = w;
        if (ch == 0) s_inv[row2] = 1.f / den;
    }
    __syncthreads();

    {
        int row2 = t >> 6, d2 = t & 63;        // 128 thr = 2 rows x 64 float2
        int growl = part * 2 + row2;
        float2 acc; acc.x = 0.f; acc.y = 0.f;
#pragma unroll
        for (int ch = 0; ch < MAXCH; ch++) {
            if (ch < nch) {
                float2 p = reinterpret_cast<const float2*>(
                    &g_pO[((size_t)(r * MAXCH + ch) * BMA + growl) * DK])[d2];
                float w = s_w[row2 * 8 + ch];
                acc.x += w * p.x;
                acc.y += w * p.y;
            }
        }
        float inv = s_inv[row2];
        acc.x *= inv; acc.y *= inv;
        reinterpret_cast<float2*>(&out[(r * BMA + growl) * DK])[d2] = acc;
    }
}

// ---------------------------------------------------------------------------
extern "C" void kernel_launch(void* const* d_in, const int* in_sizes, int n_in,
                              void* d_out, int out_size)
{
    const float* q  = (const float*)d_in[0];
    const float* k  = (const float*)d_in[1];
    const float* v  = (const float*)d_in[2];
    const float* Wq = (const float*)d_in[3];
    const float* bq = (const float*)d_in[4];
    const float* Wk = (const float*)d_in[5];
    const float* bk = (const float*)d_in[6];
    const float* Wv = (const float*)d_in[7];
    const float* bv = (const float*)d_in[8];
    float* out = (float*)d_out;

    const int smem_proj = 2 * (PM * XP + PKC * WP) * sizeof(float);        // 53248 -> 3/SM
    const int smem_attn = (6 * KST + 4 * 16 * PP) * sizeof(float);         // 113664
    cudaFuncSetAttribute(proj_part_kernel, cudaFuncAttributeMaxDynamicSharedMemorySize, smem_proj);
    cudaFuncSetAttribute(attn_part_kernel, cudaFuncAttributeMaxDynamicSharedMemorySize, smem_attn);

    proj_part_kernel<<<dim3(SEQ / PM, 3, 2), 256, smem_proj>>>(q, k, v, Wq, Wk, Wv);
    proj_reduce_kernel<<<dim3(SEQ / 32, 3), 256>>>(bq, bk, bv);
    attn_part_kernel<<<ABLOCKS, 128, smem_attn>>>(out);
    merge_kernel<<<(NTA - 8) * 32, 128>>>(out);
}

// round 17
// speedup vs baseline: 1.1835x; 1.0278x over previous
#include <cuda_runtime.h>
#include <math.h>
#include <stdint.h>

#define SEQ 4096
#define DM  1024
#define DK  128

// ---- proj tiling: split-K (2 halves), 64x128 tiles, 2-stage pipeline ----
#define PM   64
#define PKC  32
#define KHALF 16          // chunks per k-half (16 * 32 = 512)
#define XP   36           // Xs stride
#define WP   136          // Ws stride (mod 32 = 8)

// ---- attention tiling (R12 known-good) ----
#define BMA   64
#define BNA   32
#define CHUNK 512
#define NTA   (SEQ / BMA)
#define MAXCH 8
#define ABLOCKS 288       // sum_{tier=1..8} 8*tier
#define KP  136           // K/V smem stride (mod 32 = 8: LDS.64 conflict-free)
#define PP  36
#define KST (32 * KP)     // 4352 floats per buffer

// ---- scratch ----
__device__ float g_pp[3 * 2 * SEQ * DK];   // split-K proj partials (12 MB)
__device__ float g_qp[SEQ * DK];   // d-permuted within 8-col groups
__device__ float g_kp[SEQ * DK];   // d-permuted within 8-col groups
__device__ float g_vp[SEQ * DK];   // plain layout
__device__ float g_pO[NTA * MAXCH * BMA * DK];
__device__ float g_pm[NTA * MAXCH * BMA];
__device__ float g_pl[NTA * MAXCH * BMA];

__device__ __forceinline__ float f2tf(float f) {
    uint32_t u;
    asm("cvt.rn.tf32.f32 %0, %1;" : "=r"(u) : "f"(f));
    return __uint_as_float(u);
}

__device__ __forceinline__ void mma8(float& d0, float& d1, float& d2, float& d3,
                                     uint32_t a0, uint32_t a1, uint32_t a2, uint32_t a3,
                                     uint32_t b0, uint32_t b1)
{
    asm volatile(
        "mma.sync.aligned.m16n8k8.row.col.f32.tf32.tf32.f32 "
        "{%0,%1,%2,%3}, {%4,%5,%6,%7}, {%8,%9}, {%0,%1,%2,%3};\n"
        : "+f"(d0), "+f"(d1), "+f"(d2), "+f"(d3)
        : "r"(a0), "r"(a1), "r"(a2), "r"(a3), "r"(b0), "r"(b1));
}

__device__ __forceinline__ uint32_t ldu(const float* p)    { return __float_as_uint(*p); }
__device__ __forceinline__ uint32_t ldu_rn(const float* p) { return __float_as_uint(*p) + 0x1000u; }
__device__ __forceinline__ uint32_t fb(float f)            { return __float_as_uint(f); }

__device__ __forceinline__ void cp16(void* dst_smem, const void* src_gmem) {
    uint32_t d = (uint32_t)__cvta_generic_to_shared(dst_smem);
    asm volatile("cp.async.cg.shared.global [%0], [%1], 16;" :: "r"(d), "l"(src_gmem));
}
#define CP_COMMIT() asm volatile("cp.async.commit_group;")
#define CP_WAIT(n)  asm volatile("cp.async.wait_group %0;" :: "n"(n))

// ---------------------------------------------------------------------------
// Projection split-K partial (exact R15/R16): PP[which][kh] = X-half @ W-half.
// 256 thr, tile 64x128, 2-stage cp.async, grid (64, 3, 2) all co-resident.
// ---------------------------------------------------------------------------
__global__ void __launch_bounds__(256, 3) proj_part_kernel(
    const float* __restrict__ q, const float* __restrict__ k, const float* __restrict__ v,
    const float* __restrict__ Wq, const float* __restrict__ Wk, const float* __restrict__ Wv)
{
    extern __shared__ float psm[];
    float* Xb = psm;                   // 2 x 64 x 36
    float* Wb = psm + 2 * PM * XP;     // 2 x 32 x 136

    const int which = blockIdx.y;
    const int kh    = blockIdx.z;
    const float* X = (which == 0) ? q  : (which == 1) ? k  : v;
    const float* W = (which == 0) ? Wq : (which == 1) ? Wk : Wv;
    float* OUT = g_pp + (size_t)(which * 2 + kh) * SEQ * DK;

    const int t    = threadIdx.x;
    const int warp = t >> 5;
    const int lane = t & 31;
    const int wr   = warp >> 2;
    const int wc   = warp & 3;
    const int g    = lane >> 2;
    const int tig  = lane & 3;
    const int r0   = blockIdx.x * PM;
    const int kbase = kh * KHALF * PKC;     // 0 or 512

    auto issue = [&](int kc) {
        const int k0 = kbase + kc * PKC;
        float* Xs = Xb + (kc & 1) * PM * XP;
        float* Ws = Wb + (kc & 1) * PKC * WP;
#pragma unroll
        for (int i = 0; i < 2; i++) {
            int idx = t + i * 256;
            int row = idx >> 3, c4 = idx & 7;
            cp16(&Xs[row * XP + c4 * 4], &X[(r0 + row) * DM + k0 + c4 * 4]);
        }
#pragma unroll
        for (int i = 0; i < 4; i++) {
            int idx = t + i * 256;
            int row = idx >> 5, c4 = idx & 31;
            cp16(&Ws[row * WP + c4 * 4], &W[(k0 + row) * DK + c4 * 4]);
        }
        CP_COMMIT();
    };

    float acc[8][4];
#pragma unroll
    for (int i = 0; i < 8; i++)
#pragma unroll
        for (int j = 0; j < 4; j++) acc[i][j] = 0.f;

    issue(0);
    issue(1);

    for (int kc = 0; kc < KHALF; kc++) {
        if (kc + 1 < KHALF) { CP_WAIT(1); } else { CP_WAIT(0); }
        __syncthreads();

        const float* Xs = Xb + (kc & 1) * PM * XP;
        const float* Ws = Wb + (kc & 1) * PKC * WP;

#pragma unroll
        for (int ks = 0; ks < 4; ks++) {
            const int kk = ks * 8;
            uint32_t a[2][4];
#pragma unroll
            for (int mf = 0; mf < 2; mf++) {
                const float* ab = &Xs[(wr * 32 + mf * 16 + g) * XP + kk + tig];
                a[mf][0] = ldu_rn(ab);
                a[mf][1] = ldu_rn(ab + 8 * XP);
                a[mf][2] = ldu_rn(ab + 4);
                a[mf][3] = ldu_rn(ab + 8 * XP + 4);
            }
            uint32_t b[4][2];
#pragma unroll
            for (int nf = 0; nf < 4; nf++) {
                b[nf][0] = ldu_rn(&Ws[(kk + tig) * WP + wc * 32 + nf * 8 + g]);
                b[nf][1] = ldu_rn(&Ws[(kk + tig + 4) * WP + wc * 32 + nf * 8 + g]);
            }
#pragma unroll
            for (int mf = 0; mf < 2; mf++)
#pragma unroll
                for (int nf = 0; nf < 4; nf++)
                    mma8(acc[mf * 4 + nf][0], acc[mf * 4 + nf][1],
                         acc[mf * 4 + nf][2], acc[mf * 4 + nf][3],
                         a[mf][0], a[mf][1], a[mf][2], a[mf][3],
                         b[nf][0], b[nf][1]);
        }

        __syncthreads();
        if (kc + 2 < KHALF) issue(kc + 2);
    }

    // epilogue: raw fp32 partials, plain layout, float2
#pragma unroll
    for (int mf = 0; mf < 2; mf++) {
        const int row0 = r0 + wr * 32 + mf * 16 + g;
        const int row1 = row0 + 8;
#pragma unroll
        for (int nf = 0; nf < 4; nf++) {
            int col = wc * 32 + nf * 8 + 2 * tig;
            float2 o0, o1;
            o0.x = acc[mf * 4 + nf][0]; o0.y = acc[mf * 4 + nf][1];
            o1.x = acc[mf * 4 + nf][2]; o1.y = acc[mf * 4 + nf][3];
            *reinterpret_cast<float2*>(&OUT[row0 * DK + col]) = o0;
            *reinterpret_cast<float2*>(&OUT[row1 * DK + col]) = o1;
        }
    }
}

// ---------------------------------------------------------------------------
// Proj reduce (vectorized): OUT = round_tf32((P0 + P1 + b) * osc), d-permuted
// for q/k. grid (128, 3), 256 thr, float4 loads (MLP 8 per iteration).
// ---------------------------------------------------------------------------
__global__ void __launch_bounds__(256) proj_reduce_kernel(
    const float* __restrict__ bq, const float* __restrict__ bk, const float* __restrict__ bv)
{
    const int which = blockIdx.y;
    const float* B = (which == 0) ? bq : (which == 1) ? bk : bv;
    const float4* P0 = reinterpret_cast<const float4*>(
        g_pp + (size_t)(which * 2 + 0) * SEQ * DK);
    const float4* P1 = reinterpret_cast<const float4*>(
        g_pp + (size_t)(which * 2 + 1) * SEQ * DK);
    float* OUT = (which == 0) ? g_qp : (which == 1) ? g_kp : g_vp;
    const float osc = (which == 0) ? 0.08838834764831845f : 1.0f;

    const int t  = threadIdx.x;
    const int r0 = blockIdx.x * 32;
    const int base4 = r0 * 32;             // float4 index of tile start

#pragma unroll
    for (int i = 0; i < 4; i++) {
        int idx4 = t + i * 256;            // < 1024 = 32 rows x 32 float4
        int row  = r0 + (idx4 >> 5);
        int c4   = idx4 & 31;
        float4 p0 = P0[base4 + idx4];
        float4 p1 = P1[base4 + idx4];
        float4 bb = reinterpret_cast<const float4*>(B)[c4];
        float v0 = f2tf((p0.x + p1.x + bb.x) * osc);
        float v1 = f2tf((p0.y + p1.y + bb.y) * osc);
        float v2 = f2tf((p0.z + p1.z + bb.z) * osc);
        float v3 = f2tf((p0.w + p1.w + bb.w) * osc);
        if (which == 2) {
            float4 o; o.x = v0; o.y = v1; o.z = v2; o.w = v3;
            reinterpret_cast<float4*>(OUT)[base4 + idx4] = o;
        } else {
            int colb = c4 * 4;             // base column of this float4
            float vv[4] = {v0, v1, v2, v3};
#pragma unroll
            for (int e = 0; e < 4; e++) {
                int col = colb + e;
                int j = col & 7;
                int pcol = (col & ~7) | (2 * (j & 3) + (j >> 2));
                OUT[row * DK + pcol] = vv[e];
            }
        }
    }
}

// ---------------------------------------------------------------------------
// Split-KV causal flash attention partials (exact R16). nch==1 tiles (r<8)
// write normalized output directly; others write unnormalized partials.
// ---------------------------------------------------------------------------
__global__ void __launch_bounds__(128, 2) attn_part_kernel(float* __restrict__ out)
{
    extern __shared__ float sm[];
    float* Kb = sm;                 // 3 x 32 x 136
    float* Vb = sm + 3 * KST;       // 3 x 32 x 136
    float* Ps = sm + 6 * KST;       // 4 x 16 x 36

    const int t    = threadIdx.x;
    const int warp = t >> 5;
    const int lane = t & 31;
    const int g    = lane >> 2;
    const int tig  = lane & 3;
    float* Pw = Ps + warp * (16 * PP);

    // heavy-first decode: tile r has (r/8)+1 chunks
    int Bd = ABLOCKS - 1 - (int)blockIdx.x;
    int tier = 1, rem = Bd;
    while (rem >= 8 * tier) { rem -= 8 * tier; tier++; }
    const int r = (tier - 1) * 8 + rem / tier;
    const int c = rem % tier;

    const int rbase  = r * BMA;
    const int c0base = c * CHUNK;
    const int colend = min(c0base + CHUNK, rbase + BMA);
    const int nct    = (colend - c0base) / BNA;   // >= 2 always
    const int nch    = (r >> 3) + 1;

    auto issue_kv = [&](int tc) {
        const int c0 = c0base + tc * BNA;
        float* Kd = Kb + (tc % 3) * KST;
        float* Vd = Vb + ((tc + 2) % 3) * KST;
#pragma unroll
        for (int i = 0; i < 8; i++) {
            int idx = t + i * 128;
            int row = idx >> 5, c4 = idx & 31;
            cp16(&Kd[row * KP + c4 * 4], &g_kp[(c0 + row) * DK + c4 * 4]);
            cp16(&Vd[row * KP + c4 * 4], &g_vp[(c0 + row) * DK + c4 * 4]);
        }
        CP_COMMIT();
    };

    // group 1: Q -> V buffers 0,1 (64 rows)
#pragma unroll
    for (int i = 0; i < 16; i++) {
        int idx = t + i * 128;
        int row = idx >> 5, c4 = idx & 31;
        cp16(&Vb[(row >> 5) * KST + (row & 31) * KP + c4 * 4],
             &g_qp[(rbase + row) * DK + c4 * 4]);
    }
    CP_COMMIT();
    // group 2: tile 0 -> K0, V2
    issue_kv(0);
    CP_WAIT(1);           // Q landed
    __syncthreads();

    // cache Q A-fragments (permuted layout -> float2)
    uint32_t qf[16][4];
    {
        const float* Qsrc = Vb + (warp >> 1) * KST;
        const int row_l = (warp & 1) * 16 + g;
#pragma unroll
        for (int ks = 0; ks < 16; ks++) {
            float2 qa = *reinterpret_cast<const float2*>(&Qsrc[row_l * KP + ks * 8 + 2 * tig]);
            float2 qb = *reinterpret_cast<const float2*>(&Qsrc[(row_l + 8) * KP + ks * 8 + 2 * tig]);
            qf[ks][0] = fb(qa.x);
            qf[ks][1] = fb(qb.x);
            qf[ks][2] = fb(qa.y);
            qf[ks][3] = fb(qb.y);
        }
    }
    __syncthreads();      // V0/V1 free
    issue_kv(1);          // tile 1 -> K1, V0

    float o[16][4];
#pragma unroll
    for (int nt = 0; nt < 16; nt++)
#pragma unroll
        for (int j = 0; j < 4; j++) o[nt][j] = 0.f;

    float m0 = -1e30f, m1 = -1e30f, l0 = 0.f, l1 = 0.f;
    const int grow0 = rbase + warp * 16 + g;
    const int grow1 = grow0 + 8;

    for (int tc = 0; tc < nct; tc++) {
        const int c0 = c0base + tc * BNA;
        if (tc + 1 < nct) { CP_WAIT(1); } else { CP_WAIT(0); }
        __syncthreads();
        if (tc + 2 < nct) issue_kv(tc + 2);

        const float* Ks = Kb + (tc % 3) * KST;
        const float* Vs = Vb + ((tc + 2) % 3) * KST;

        // ---- S = Q K^T ----
        float s[4][4];
#pragma unroll
        for (int nt = 0; nt < 4; nt++)
#pragma unroll
            for (int j = 0; j < 4; j++) s[nt][j] = 0.f;

#pragma unroll
        for (int ks = 0; ks < 16; ks++) {
            const int kk = ks * 8;
#pragma unroll
            for (int nt = 0; nt < 4; nt++) {
                float2 kv = *reinterpret_cast<const float2*>(&Ks[(nt * 8 + g) * KP + kk + 2 * tig]);
                mma8(s[nt][0], s[nt][1], s[nt][2], s[nt][3],
                     qf[ks][0], qf[ks][1], qf[ks][2], qf[ks][3],
                     fb(kv.x), fb(kv.y));
            }
        }

        // ---- causal mask + online softmax ----
        float mloc0 = -1e30f, mloc1 = -1e30f;
#pragma unroll
        for (int nt = 0; nt < 4; nt++) {
            int colb = c0 + nt * 8 + 2 * tig;
            float x0 = (colb     <= grow0) ? s[nt][0] : -1e30f;
            float x1 = (colb + 1 <= grow0) ? s[nt][1] : -1e30f;
            float x2 = (colb     <= grow1) ? s[nt][2] : -1e30f;
            float x3 = (colb + 1 <= grow1) ? s[nt][3] : -1e30f;
            s[nt][0] = x0; s[nt][1] = x1; s[nt][2] = x2; s[nt][3] = x3;
            mloc0 = fmaxf(mloc0, fmaxf(x0, x1));
            mloc1 = fmaxf(mloc1, fmaxf(x2, x3));
        }
        mloc0 = fmaxf(mloc0, __shfl_xor_sync(0xffffffffu, mloc0, 1));
        mloc0 = fmaxf(mloc0, __shfl_xor_sync(0xffffffffu, mloc0, 2));
        mloc1 = fmaxf(mloc1, __shfl_xor_sync(0xffffffffu, mloc1, 1));
        mloc1 = fmaxf(mloc1, __shfl_xor_sync(0xffffffffu, mloc1, 2));

        float mn0 = fmaxf(m0, mloc0);
        float mn1 = fmaxf(m1, mloc1);
        float sc0 = __expf(m0 - mn0);
        float sc1 = __expf(m1 - mn1);

        float ps0 = 0.f, ps1 = 0.f;
#pragma unroll
        for (int nt = 0; nt < 4; nt++) {
            float p0 = __expf(s[nt][0] - mn0);
            float p1 = __expf(s[nt][1] - mn0);
            float p2 = __expf(s[nt][2] - mn1);
            float p3 = __expf(s[nt][3] - mn1);
            ps0 += p0 + p1;
            ps1 += p2 + p3;
            float* d0 = &Pw[g * PP + nt * 8 + 2 * tig];
            d0[0] = f2tf(p0); d0[1] = f2tf(p1);
            float* d1 = &Pw[(g + 8) * PP + nt * 8 + 2 * tig];
            d1[0] = f2tf(p2); d1[1] = f2tf(p3);
        }
        ps0 += __shfl_xor_sync(0xffffffffu, ps0, 1);
        ps0 += __shfl_xor_sync(0xffffffffu, ps0, 2);
        ps1 += __shfl_xor_sync(0xffffffffu, ps1, 1);
        ps1 += __shfl_xor_sync(0xffffffffu, ps1, 2);

        l0 = l0 * sc0 + ps0;  m0 = mn0;
        l1 = l1 * sc1 + ps1;  m1 = mn1;

        __syncwarp();

        // ---- rescale O, then O += P @ V ----
#pragma unroll
        for (int nt = 0; nt < 16; nt++) {
            o[nt][0] *= sc0; o[nt][1] *= sc0;
            o[nt][2] *= sc1; o[nt][3] *= sc1;
        }

#pragma unroll
        for (int ks = 0; ks < 4; ks++) {
            const int kk = ks * 8;
            const float* ab = &Pw[g * PP + kk + tig];
            uint32_t a0 = ldu(ab);
            uint32_t a1 = ldu(ab + 8 * PP);
            uint32_t a2 = ldu(ab + 4);
            uint32_t a3 = ldu(ab + 8 * PP + 4);
#pragma unroll
            for (int nt = 0; nt < 16; nt++) {
                uint32_t b0 = ldu(&Vs[(kk + tig) * KP + nt * 8 + g]);
                uint32_t b1 = ldu(&Vs[(kk + tig + 4) * KP + nt * 8 + g]);
                mma8(o[nt][0], o[nt][1], o[nt][2], o[nt][3], a0, a1, a2, a3, b0, b1);
            }
        }
    }

    const int row0 = warp * 16 + g;
    const int row1 = row0 + 8;

    // ---- single-chunk tiles (r<8): write normalized output directly ----
    if (nch == 1) {
        float inv0 = 1.f / l0;
        float inv1 = 1.f / l1;
#pragma unroll
        for (int nt = 0; nt < 16; nt++) {
            int col = nt * 8 + 2 * tig;
            float2 w0; w0.x = o[nt][0] * inv0; w0.y = o[nt][1] * inv0;
            float2 w1; w1.x = o[nt][2] * inv1; w1.y = o[nt][3] * inv1;
            *reinterpret_cast<float2*>(&out[(rbase + row0) * DK + col]) = w0;
            *reinterpret_cast<float2*>(&out[(rbase + row1) * DK + col]) = w1;
        }
        return;
    }

    // ---- write unnormalized partials ----
    const int pidx = r * MAXCH + c;
    float* baseO = &g_pO[(size_t)pidx * BMA * DK];
#pragma unroll
    for (int nt = 0; nt < 16; nt++) {
        int col = nt * 8 + 2 * tig;
        float2 w0; w0.x = o[nt][0]; w0.y = o[nt][1];
        float2 w1; w1.x = o[nt][2]; w1.y = o[nt][3];
        *reinterpret_cast<float2*>(&baseO[row0 * DK + col]) = w0;
        *reinterpret_cast<float2*>(&baseO[row1 * DK + col]) = w1;
    }
    if (tig == 0) {
        g_pm[pidx * BMA + row0] = m0;
        g_pm[pidx * BMA + row1] = m1;
        g_pl[pidx * BMA + row0] = l0;
        g_pl[pidx * BMA + row1] = l1;
    }
}

// ---------------------------------------------------------------------------
// Merge (exact R16): tiles r in [8, 64). 1792 blocks, 2 rows x 128 d each.
// ---------------------------------------------------------------------------
__global__ void __launch_bounds__(128) merge_kernel(float* __restrict__ out)
{
    __shared__ float s_w[2 * MAXCH];
    __shared__ float s_inv[2];

    const int r    = 8 + (blockIdx.x >> 5);   // 8..63
    const int part = blockIdx.x & 31;         // 0..31 (2 rows each)
    const int nch  = (r >> 3) + 1;            // 2..8
    const int t    = threadIdx.x;

    if (t < 16) {
        int row2 = t >> 3, ch = t & 7;
        float mv = -1e30f, lv = 0.f;
        if (ch < nch) {
            mv = g_pm[(r * MAXCH + ch) * BMA + part * 2 + row2];
            lv = g_pl[(r * MAXCH + ch) * BMA + part * 2 + row2];
        }
        float mx = mv;
        mx = fmaxf(mx, __shfl_xor_sync(0x0000ffffu, mx, 4));
        mx = fmaxf(mx, __shfl_xor_sync(0x0000ffffu, mx, 2));
        mx = fmaxf(mx, __shfl_xor_sync(0x0000ffffu, mx, 1));
        float w = (ch < nch) ? __expf(mv - mx) : 0.f;
        float den = w * lv;
        den += __shfl_xor_sync(0x0000ffffu, den, 4);
        den += __shfl_xor_sync(0x0000ffffu, den, 2);
        den += __shfl_xor_sync(0x0000ffffu, den, 1);
        s_w[t] = w;
        if (ch == 0) s_inv[row2] = 1.f / den;
    }
    __syncthreads();

    {
        int row2 = t >> 6, d2 = t & 63;        // 128 thr = 2 rows x 64 float2
        int growl = part * 2 + row2;
        float2 acc; acc.x = 0.f; acc.y = 0.f;
#pragma unroll
        for (int ch = 0; ch < MAXCH; ch++) {
            if (ch < nch) {
                float2 p = reinterpret_cast<const float2*>(
                    &g_pO[((size_t)(r * MAXCH + ch) * BMA + growl) * DK])[d2];
                float w = s_w[row2 * 8 + ch];
                acc.x += w * p.x;
                acc.y += w * p.y;
            }
        }
        float inv = s_inv[row2];
        acc.x *= inv; acc.y *= inv;
        reinterpret_cast<float2*>(&out[(r * BMA + growl) * DK])[d2] = acc;
    }
}

// ---------------------------------------------------------------------------
extern "C" void kernel_launch(void* const* d_in, const int* in_sizes, int n_in,
                              void* d_out, int out_size)
{
    const float* q  = (const float*)d_in[0];
    const float* k  = (const float*)d_in[1];
    const float* v  = (const float*)d_in[2];
    const float* Wq = (const float*)d_in[3];
    const float* bq = (const float*)d_in[4];
    const float* Wk = (const float*)d_in[5];
    const float* bk = (const float*)d_in[6];
    const float* Wv = (const float*)d_in[7];
    const float* bv = (const float*)d_in[8];
    float* out = (float*)d_out;

    const int smem_proj = 2 * (PM * XP + PKC * WP) * sizeof(float);        // 53248 -> 3/SM
    const int smem_attn = (6 * KST + 4 * 16 * PP) * sizeof(float);         // 113664
    cudaFuncSetAttribute(proj_part_kernel, cudaFuncAttributeMaxDynamicSharedMemorySize, smem_proj);
    cudaFuncSetAttribute(attn_part_kernel, cudaFuncAttributeMaxDynamicSharedMemorySize, smem_attn);

    proj_part_kernel<<<dim3(SEQ / PM, 3, 2), 256, smem_proj>>>(q, k, v, Wq, Wk, Wv);
    proj_reduce_kernel<<<dim3(SEQ / 32, 3), 256>>>(bq, bk, bv);
    attn_part_kernel<<<ABLOCKS, 128, smem_attn>>>(out);
    merge_kernel<<<(NTA - 8) * 32, 128>>>(out);
}